// round 16
// baseline (speedup 1.0000x reference)
#include <cuda_runtime.h>

// QuantumAttentionLayer — analytic collapse (see R11 derivation):
//   <Z_i> = -sin(ry_theta[i])  (batch- and data-independent)
//   row[j] = sum_k (-sin(ry[k])) * W[j*20+k] + bias[j]
// broadcast across all 4096 output rows.
//
// Latency-optimized: warp 0 does the whole dependent computation with ALL
// loads issued up front (one memory round trip), __sinf (MUFU) for the sins,
// a single __syncthreads, then every thread emits one LDS.128 + STG.128.

#define NQUBIT 20
#define BATCH  4096
#define THREADS 256
#define OUT_FLOAT4 ((BATCH * NQUBIT) / 4)   // 20480
#define BLOCKS  (OUT_FLOAT4 / THREADS)      // 80

__global__ void __launch_bounds__(THREADS)
qattn_broadcast_kernel(const float* __restrict__ ry,
                       const float* __restrict__ W,
                       const float* __restrict__ bias,
                       float4* __restrict__ out) {
    __shared__ __align__(16) float row[NQUBIT];

    const int tid = threadIdx.x;

    if (tid < NQUBIT) {
        // --- all loads issued up front, fully independent (one round trip) ---
        const float4* ry4 = (const float4*)ry;
        const float4 a0 = ry4[0], a1 = ry4[1], a2 = ry4[2], a3 = ry4[3], a4 = ry4[4];

        const float4* wr = (const float4*)(W + tid * NQUBIT);  // tid*20 floats: 16B aligned
        const float4 w0 = wr[0], w1 = wr[1], w2 = wr[2], w3 = wr[3], w4 = wr[4];

        float acc = bias[tid];

        // --- sins (MUFU) + dot product; 4-way independent partial sums ---
        float p0 = -__sinf(a0.x) * w0.x;
        float p1 = -__sinf(a0.y) * w0.y;
        float p2 = -__sinf(a0.z) * w0.z;
        float p3 = -__sinf(a0.w) * w0.w;
        p0 = fmaf(-__sinf(a1.x), w1.x, p0);
        p1 = fmaf(-__sinf(a1.y), w1.y, p1);
        p2 = fmaf(-__sinf(a1.z), w1.z, p2);
        p3 = fmaf(-__sinf(a1.w), w1.w, p3);
        p0 = fmaf(-__sinf(a2.x), w2.x, p0);
        p1 = fmaf(-__sinf(a2.y), w2.y, p1);
        p2 = fmaf(-__sinf(a2.z), w2.z, p2);
        p3 = fmaf(-__sinf(a2.w), w2.w, p3);
        p0 = fmaf(-__sinf(a3.x), w3.x, p0);
        p1 = fmaf(-__sinf(a3.y), w3.y, p1);
        p2 = fmaf(-__sinf(a3.z), w3.z, p2);
        p3 = fmaf(-__sinf(a3.w), w3.w, p3);
        p0 = fmaf(-__sinf(a4.x), w4.x, p0);
        p1 = fmaf(-__sinf(a4.y), w4.y, p1);
        p2 = fmaf(-__sinf(a4.z), w4.z, p2);
        p3 = fmaf(-__sinf(a4.w), w4.w, p3);

        row[tid] = acc + ((p0 + p1) + (p2 + p3));
    }
    __syncthreads();

    // One float4 per thread, fully coalesced. base = (4g) % 20 is a multiple
    // of 4, so the shared read is an aligned LDS.128 and the float4 never
    // crosses a row-copy boundary.
    const int g = blockIdx.x * THREADS + tid;   // 0 .. 20479
    const int base = (4 * g) % NQUBIT;
    out[g] = *(const float4*)&row[base];
}

extern "C" void kernel_launch(void* const* d_in, const int* in_sizes, int n_in,
                              void* d_out, int out_size) {
    // metadata order: query, key, value, ry_theta, rz_theta, W, b
    const float* ry   = (const float*)d_in[3];   // 20 floats
    const float* W    = (const float*)d_in[5];   // (20, 20)
    const float* bias = (const float*)d_in[6];   // (20,)
    (void)in_sizes; (void)n_in; (void)out_size;

    qattn_broadcast_kernel<<<BLOCKS, THREADS>>>(ry, W, bias, (float4*)d_out);
}

// round 17
// speedup vs baseline: 1.0435x; 1.0435x over previous
#include <cuda_runtime.h>

// QuantumAttentionLayer — analytic collapse (see R11 derivation):
//   <Z_i> = -sin(ry_theta[i])  (batch- and data-independent)
//   row[j] = sum_k (-sin(ry[k])) * W[j*20+k] + bias[j]
// broadcast across all 4096 output rows.
//
// Latency-optimized: warp 0 does the whole dependent computation with ALL
// loads issued up front (one memory round trip), __sinf (MUFU) for the sins,
// a single __syncthreads, then every thread emits one LDS.128 + STG.128.

#define NQUBIT 20
#define BATCH  4096
#define THREADS 256
#define OUT_FLOAT4 ((BATCH * NQUBIT) / 4)   // 20480
#define BLOCKS  (OUT_FLOAT4 / THREADS)      // 80

__global__ void __launch_bounds__(THREADS)
qattn_broadcast_kernel(const float* __restrict__ ry,
                       const float* __restrict__ W,
                       const float* __restrict__ bias,
                       float4* __restrict__ out) {
    __shared__ __align__(16) float row[NQUBIT];

    const int tid = threadIdx.x;

    if (tid < NQUBIT) {
        // --- all loads issued up front, fully independent (one round trip) ---
        const float4* ry4 = (const float4*)ry;
        const float4 a0 = ry4[0], a1 = ry4[1], a2 = ry4[2], a3 = ry4[3], a4 = ry4[4];

        const float4* wr = (const float4*)(W + tid * NQUBIT);  // tid*20 floats: 16B aligned
        const float4 w0 = wr[0], w1 = wr[1], w2 = wr[2], w3 = wr[3], w4 = wr[4];

        float acc = bias[tid];

        // --- sins (MUFU) + dot product; 4-way independent partial sums ---
        float p0 = -__sinf(a0.x) * w0.x;
        float p1 = -__sinf(a0.y) * w0.y;
        float p2 = -__sinf(a0.z) * w0.z;
        float p3 = -__sinf(a0.w) * w0.w;
        p0 = fmaf(-__sinf(a1.x), w1.x, p0);
        p1 = fmaf(-__sinf(a1.y), w1.y, p1);
        p2 = fmaf(-__sinf(a1.z), w1.z, p2);
        p3 = fmaf(-__sinf(a1.w), w1.w, p3);
        p0 = fmaf(-__sinf(a2.x), w2.x, p0);
        p1 = fmaf(-__sinf(a2.y), w2.y, p1);
        p2 = fmaf(-__sinf(a2.z), w2.z, p2);
        p3 = fmaf(-__sinf(a2.w), w2.w, p3);
        p0 = fmaf(-__sinf(a3.x), w3.x, p0);
        p1 = fmaf(-__sinf(a3.y), w3.y, p1);
        p2 = fmaf(-__sinf(a3.z), w3.z, p2);
        p3 = fmaf(-__sinf(a3.w), w3.w, p3);
        p0 = fmaf(-__sinf(a4.x), w4.x, p0);
        p1 = fmaf(-__sinf(a4.y), w4.y, p1);
        p2 = fmaf(-__sinf(a4.z), w4.z, p2);
        p3 = fmaf(-__sinf(a4.w), w4.w, p3);

        row[tid] = acc + ((p0 + p1) + (p2 + p3));
    }
    __syncthreads();

    // One float4 per thread, fully coalesced. base = (4g) % 20 is a multiple
    // of 4, so the shared read is an aligned LDS.128 and the float4 never
    // crosses a row-copy boundary.
    const int g = blockIdx.x * THREADS + tid;   // 0 .. 20479
    const int base = (4 * g) % NQUBIT;
    out[g] = *(const float4*)&row[base];
}

extern "C" void kernel_launch(void* const* d_in, const int* in_sizes, int n_in,
                              void* d_out, int out_size) {
    // metadata order: query, key, value, ry_theta, rz_theta, W, b
    const float* ry   = (const float*)d_in[3];   // 20 floats
    const float* W    = (const float*)d_in[5];   // (20, 20)
    const float* bias = (const float*)d_in[6];   // (20,)
    (void)in_sizes; (void)n_in; (void)out_size;

    qattn_broadcast_kernel<<<BLOCKS, THREADS>>>(ry, W, bias, (float4*)d_out);
}